// round 1
// baseline (speedup 1.0000x reference)
#include <cuda_runtime.h>
#include <math_constants.h>

#define BB 64
#define LL 4096
#define DD 512
#define NS 8                 // L-splits per batch row
#define CHUNK (LL / NS)      // 512 rows per CTA
#define WARPS 8
#define NTHREADS (WARPS * 32)

// scratch: per (b, split): c[512] at local-max reference, then m, then s
__device__ float g_scratch[BB * NS * (DD + 2)];

__global__ void __launch_bounds__(NTHREADS)
attn_pass1(const float* __restrict__ h, const float* __restrict__ E) {
    const int b     = blockIdx.x / NS;
    const int split = blockIdx.x % NS;
    const int tid   = threadIdx.x;
    const int wid   = tid >> 5;
    const int lane  = tid & 31;

    // load h[b] (512 floats): lane j holds float4 indices j + 32q
    const float4* h4 = (const float4*)(h + (size_t)b * DD);
    float4 hv[4];
#pragma unroll
    for (int q = 0; q < 4; q++) hv[q] = h4[lane + 32 * q];

    const float4* Eb  = (const float4*)(E + (size_t)b * LL * DD);
    const int row0    = split * CHUNK;

    float m = -CUDART_INF_F;
    float s = 0.f;
    float4 c[4];
#pragma unroll
    for (int q = 0; q < 4; q++) c[q] = make_float4(0.f, 0.f, 0.f, 0.f);

    for (int r = wid; r < CHUNK; r += WARPS) {
        const float4* row = Eb + (size_t)(row0 + r) * (DD / 4);
        float4 v[4];
#pragma unroll
        for (int q = 0; q < 4; q++) v[q] = row[lane + 32 * q];

        // partial dot (16 FMA)
        float dot = 0.f;
#pragma unroll
        for (int q = 0; q < 4; q++) {
            dot = fmaf(v[q].x, hv[q].x, dot);
            dot = fmaf(v[q].y, hv[q].y, dot);
            dot = fmaf(v[q].z, hv[q].z, dot);
            dot = fmaf(v[q].w, hv[q].w, dot);
        }
        // warp reduction -> e known by all lanes
#pragma unroll
        for (int o = 16; o > 0; o >>= 1)
            dot += __shfl_xor_sync(0xffffffffu, dot, o);
        const float e = dot;

        if (e > m) {                       // warp-uniform, rarely taken after warmup
            const float sc = __expf(m - e);
            s *= sc;
#pragma unroll
            for (int q = 0; q < 4; q++) {
                c[q].x *= sc; c[q].y *= sc; c[q].z *= sc; c[q].w *= sc;
            }
            m = e;
        }
        const float p = __expf(e - m);
        s += p;
#pragma unroll
        for (int q = 0; q < 4; q++) {
            c[q].x = fmaf(p, v[q].x, c[q].x);
            c[q].y = fmaf(p, v[q].y, c[q].y);
            c[q].z = fmaf(p, v[q].z, c[q].z);
            c[q].w = fmaf(p, v[q].w, c[q].w);
        }
    }

    // ---- combine the 8 warps within the CTA ----
    __shared__ float sm_c[WARPS][DD];
    __shared__ float sm_m[WARPS], sm_s[WARPS], sm_sc[WARPS];
    __shared__ float sm_mg, sm_stot;

#pragma unroll
    for (int q = 0; q < 4; q++) {
        const int d0 = 4 * lane + 128 * q;
        sm_c[wid][d0 + 0] = c[q].x;
        sm_c[wid][d0 + 1] = c[q].y;
        sm_c[wid][d0 + 2] = c[q].z;
        sm_c[wid][d0 + 3] = c[q].w;
    }
    if (lane == 0) { sm_m[wid] = m; sm_s[wid] = s; }
    __syncthreads();

    if (wid == 0) {
        float mw = (lane < WARPS) ? sm_m[lane] : -CUDART_INF_F;
        float mg = mw;
#pragma unroll
        for (int o = 16; o > 0; o >>= 1)
            mg = fmaxf(mg, __shfl_xor_sync(0xffffffffu, mg, o));
        float sc = (lane < WARPS) ? __expf(mw - mg) : 0.f;
        float st = (lane < WARPS) ? sm_s[lane] * sc : 0.f;
#pragma unroll
        for (int o = 16; o > 0; o >>= 1)
            st += __shfl_xor_sync(0xffffffffu, st, o);
        if (lane < WARPS) sm_sc[lane] = sc;
        if (lane == 0) { sm_mg = mg; sm_stot = st; }
    }
    __syncthreads();

    float* out = g_scratch + ((size_t)b * NS + split) * (DD + 2);
    for (int d = tid; d < DD; d += NTHREADS) {
        float acc = 0.f;
#pragma unroll
        for (int w = 0; w < WARPS; w++)
            acc = fmaf(sm_c[w][d], sm_sc[w], acc);
        out[d] = acc;
    }
    if (tid == 0) { out[DD] = sm_mg; out[DD + 1] = sm_stot; }
}

__global__ void __launch_bounds__(256)
attn_pass2(float* __restrict__ outp) {
    const int b   = blockIdx.x;
    const int tid = threadIdx.x;

    __shared__ float sm_sc[NS];
    __shared__ float sm_stot;

    if (tid < 32) {
        const float* base = g_scratch + (size_t)b * NS * (DD + 2);
        float mw = (tid < NS) ? base[(size_t)tid * (DD + 2) + DD] : -CUDART_INF_F;
        float mg = mw;
#pragma unroll
        for (int o = 16; o > 0; o >>= 1)
            mg = fmaxf(mg, __shfl_xor_sync(0xffffffffu, mg, o));
        float sc = (tid < NS) ? __expf(mw - mg) : 0.f;
        float st = (tid < NS) ? base[(size_t)tid * (DD + 2) + DD + 1] * sc : 0.f;
#pragma unroll
        for (int o = 16; o > 0; o >>= 1)
            st += __shfl_xor_sync(0xffffffffu, st, o);
        if (tid < NS) sm_sc[tid] = sc;
        if (tid == 0) sm_stot = st;
    }
    __syncthreads();

    const float inv = 1.f / (sm_stot * (float)LL);
    const float* base = g_scratch + (size_t)b * NS * (DD + 2);
    for (int d = tid; d < DD; d += 256) {
        float acc = 0.f;
#pragma unroll
        for (int w = 0; w < NS; w++)
            acc = fmaf(base[(size_t)w * (DD + 2) + d], sm_sc[w], acc);
        outp[(size_t)b * DD + d] = acc * inv;
    }
}

extern "C" void kernel_launch(void* const* d_in, const int* in_sizes, int n_in,
                              void* d_out, int out_size) {
    const float* h = (const float*)d_in[0];   // current_hidden [64, 512]
    const float* E = (const float*)d_in[1];   // encoder_outputs [64, 4096, 512]
    float* outp = (float*)d_out;              // [64, 512]

    attn_pass1<<<BB * NS, NTHREADS>>>(h, E);
    attn_pass2<<<BB, 256>>>(outp);
}

// round 2
// speedup vs baseline: 1.0078x; 1.0078x over previous
#include <cuda_runtime.h>
#include <math_constants.h>

#define BB 64
#define LL 4096
#define DD 512
#define NS 4                 // L-splits per batch row -> grid 256 = single wave
#define CHUNK (LL / NS)      // 1024 rows per CTA
#define WARPS 8
#define NTHREADS (WARPS * 32)

// scratch: per (b, split): c[512] at local-max reference, then m, then s
__device__ float g_scratch[BB * NS * (DD + 2)];

__global__ void __launch_bounds__(NTHREADS, 2)
attn_pass1(const float* __restrict__ h, const float* __restrict__ E) {
    const int b     = blockIdx.x / NS;
    const int split = blockIdx.x % NS;
    const int tid   = threadIdx.x;
    const int wid   = tid >> 5;
    const int lane  = tid & 31;

    // load h[b] (512 floats): lane j holds float4 indices j + 32q
    const float4* h4 = (const float4*)(h + (size_t)b * DD);
    float4 hv[4];
#pragma unroll
    for (int q = 0; q < 4; q++) hv[q] = h4[lane + 32 * q];

    const float4* Eb  = (const float4*)(E + (size_t)b * LL * DD);
    const int row0    = split * CHUNK;

    float m = -CUDART_INF_F;
    float s = 0.f;
    float4 c[4];
#pragma unroll
    for (int q = 0; q < 4; q++) c[q] = make_float4(0.f, 0.f, 0.f, 0.f);

    // two rows per warp-iteration: ILP across the two shuffle reductions,
    // 8 outstanding LDG.128 at iteration front
    for (int p = wid; p < CHUNK / 2; p += WARPS) {
        const float4* rowA = Eb + (size_t)(row0 + 2 * p) * (DD / 4);
        const float4* rowB = rowA + (DD / 4);
        float4 vA[4], vB[4];
#pragma unroll
        for (int q = 0; q < 4; q++) vA[q] = rowA[lane + 32 * q];
#pragma unroll
        for (int q = 0; q < 4; q++) vB[q] = rowB[lane + 32 * q];

        float d0 = 0.f, d1 = 0.f;
#pragma unroll
        for (int q = 0; q < 4; q++) {
            d0 = fmaf(vA[q].x, hv[q].x, d0);
            d1 = fmaf(vB[q].x, hv[q].x, d1);
            d0 = fmaf(vA[q].y, hv[q].y, d0);
            d1 = fmaf(vB[q].y, hv[q].y, d1);
            d0 = fmaf(vA[q].z, hv[q].z, d0);
            d1 = fmaf(vB[q].z, hv[q].z, d1);
            d0 = fmaf(vA[q].w, hv[q].w, d0);
            d1 = fmaf(vB[q].w, hv[q].w, d1);
        }
        // interleaved warp reductions (two independent chains)
#pragma unroll
        for (int o = 16; o > 0; o >>= 1) {
            d0 += __shfl_xor_sync(0xffffffffu, d0, o);
            d1 += __shfl_xor_sync(0xffffffffu, d1, o);
        }
        const float e0 = d0, e1 = d1;
        const float emax = fmaxf(e0, e1);

        if (emax > m) {                    // warp-uniform, rarely taken after warmup
            const float sc = __expf(m - emax);
            s *= sc;
#pragma unroll
            for (int q = 0; q < 4; q++) {
                c[q].x *= sc; c[q].y *= sc; c[q].z *= sc; c[q].w *= sc;
            }
            m = emax;
        }
        const float p0 = __expf(e0 - m);
        const float p1 = __expf(e1 - m);
        s += p0 + p1;
#pragma unroll
        for (int q = 0; q < 4; q++) {
            c[q].x = fmaf(p0, vA[q].x, c[q].x);
            c[q].y = fmaf(p0, vA[q].y, c[q].y);
            c[q].z = fmaf(p0, vA[q].z, c[q].z);
            c[q].w = fmaf(p0, vA[q].w, c[q].w);
            c[q].x = fmaf(p1, vB[q].x, c[q].x);
            c[q].y = fmaf(p1, vB[q].y, c[q].y);
            c[q].z = fmaf(p1, vB[q].z, c[q].z);
            c[q].w = fmaf(p1, vB[q].w, c[q].w);
        }
    }

    // ---- combine the 8 warps within the CTA ----
    __shared__ float sm_c[WARPS][DD];
    __shared__ float sm_m[WARPS], sm_s[WARPS], sm_sc[WARPS];
    __shared__ float sm_mg, sm_stot;

#pragma unroll
    for (int q = 0; q < 4; q++) {
        const int d0i = 4 * lane + 128 * q;
        sm_c[wid][d0i + 0] = c[q].x;
        sm_c[wid][d0i + 1] = c[q].y;
        sm_c[wid][d0i + 2] = c[q].z;
        sm_c[wid][d0i + 3] = c[q].w;
    }
    if (lane == 0) { sm_m[wid] = m; sm_s[wid] = s; }
    __syncthreads();

    if (wid == 0) {
        float mw = (lane < WARPS) ? sm_m[lane] : -CUDART_INF_F;
        float mg = mw;
#pragma unroll
        for (int o = 16; o > 0; o >>= 1)
            mg = fmaxf(mg, __shfl_xor_sync(0xffffffffu, mg, o));
        float sc = (lane < WARPS) ? __expf(mw - mg) : 0.f;
        float st = (lane < WARPS) ? sm_s[lane] * sc : 0.f;
#pragma unroll
        for (int o = 16; o > 0; o >>= 1)
            st += __shfl_xor_sync(0xffffffffu, st, o);
        if (lane < WARPS) sm_sc[lane] = sc;
        if (lane == 0) { sm_mg = mg; sm_stot = st; }
    }
    __syncthreads();

    float* out = g_scratch + ((size_t)b * NS + split) * (DD + 2);
    for (int d = tid; d < DD; d += NTHREADS) {
        float acc = 0.f;
#pragma unroll
        for (int w = 0; w < WARPS; w++)
            acc = fmaf(sm_c[w][d], sm_sc[w], acc);
        out[d] = acc;
    }
    if (tid == 0) { out[DD] = sm_mg; out[DD + 1] = sm_stot; }
}

// 256 blocks x 128 threads: block (b, quarter) handles 128 d-values
__global__ void __launch_bounds__(128)
attn_pass2(float* __restrict__ outp) {
    const int b    = blockIdx.x >> 2;
    const int quad = blockIdx.x & 3;
    const int tid  = threadIdx.x;

    __shared__ float sm_sc[NS];
    __shared__ float sm_stot;

    const float* base = g_scratch + (size_t)b * NS * (DD + 2);

    if (tid < 32) {
        float mw = (tid < NS) ? base[(size_t)tid * (DD + 2) + DD] : -CUDART_INF_F;
        float mg = mw;
#pragma unroll
        for (int o = 16; o > 0; o >>= 1)
            mg = fmaxf(mg, __shfl_xor_sync(0xffffffffu, mg, o));
        float sc = (tid < NS) ? __expf(mw - mg) : 0.f;
        float st = (tid < NS) ? base[(size_t)tid * (DD + 2) + DD + 1] * sc : 0.f;
#pragma unroll
        for (int o = 16; o > 0; o >>= 1)
            st += __shfl_xor_sync(0xffffffffu, st, o);
        if (tid < NS) sm_sc[tid] = sc;
        if (tid == 0) sm_stot = st;
    }
    __syncthreads();

    const float inv = 1.f / (sm_stot * (float)LL);
    const int d = quad * 128 + tid;
    float acc = 0.f;
#pragma unroll
    for (int w = 0; w < NS; w++)
        acc = fmaf(base[(size_t)w * (DD + 2) + d], sm_sc[w], acc);
    outp[(size_t)b * DD + d] = acc * inv;
}

extern "C" void kernel_launch(void* const* d_in, const int* in_sizes, int n_in,
                              void* d_out, int out_size) {
    const float* h = (const float*)d_in[0];   // current_hidden [64, 512]
    const float* E = (const float*)d_in[1];   // encoder_outputs [64, 4096, 512]
    float* outp = (float*)d_out;              // [64, 512]

    attn_pass1<<<BB * NS, NTHREADS>>>(h, E);
    attn_pass2<<<BB * 4, 128>>>(outp);
}